// round 15
// baseline (speedup 1.0000x reference)
#include <cuda_runtime.h>
#include <cuda_bf16.h>
#include <cstdint>

// Problem constants: B=256, IN=64, HID=128, OUT=64, T=1000
// Output: ys (B,T,64) then hs (B,T,128), float32.

typedef unsigned long long ull;

// ------------------------- device scratch (no allocs allowed) --------------
__device__ float g_ximp[256 * 64 * 1000];                 // imputed x (B,IN,T)
__device__ float g_pre[131072000];                        // (B,T,[gamH,preZ,preR,preH],128)

// ------------------------- helpers -----------------------------------------
__device__ __forceinline__ void fma2(ull& d, ull a, ull b) {
    asm("fma.rn.f32x2 %0, %1, %2, %0;" : "+l"(d) : "l"(a), "l"(b));
}
__device__ __forceinline__ ull pk2(float lo, float hi) {
    ull r;
    asm("mov.b64 %0, {%1, %2};" : "=l"(r) : "f"(lo), "f"(hi));
    return r;
}
__device__ __forceinline__ float2 up2(ull v) {
    float2 r;
    asm("mov.b64 {%0, %1}, %2;" : "=f"(r.x), "=f"(r.y) : "l"(v));
    return r;
}
__device__ __forceinline__ float sigf(float x) { return 1.f / (1.f + __expf(-x)); }
__device__ __forceinline__ float tanhf_(float x) { return 1.f - 2.f / (1.f + __expf(2.f * x)); }

// ============================================================================
// K1: imputation. One CTA per batch. gamma_x GEMM + LOCF scan + impute.
// (unchanged)
// ============================================================================
__global__ void __launch_bounds__(256) k1_impute(
    const float* __restrict__ inp, const float* __restrict__ xmean,
    const float* __restrict__ Wdgx, const float* __restrict__ bdgx)
{
    extern __shared__ float sm_[];
    float* sx  = sm_;                 // 64 x 129
    float* smk = sx + 64 * 129;
    float* sd  = smk + 64 * 129;
    float* sg  = sd + 64 * 129;
    float* sW  = sg + 64 * 129;       // 64 x 64
    const int b = blockIdx.x, tid = threadIdx.x;

    for (int e = tid; e < 64 * 64; e += 256) sW[e] = Wdgx[e];
    float xl  = 0.f;
    float xmn = (tid < 64) ? xmean[tid] : 0.f;

    for (int t0 = 0; t0 < 1000; t0 += 128) {
        const int nv = min(128, 1000 - t0);
        __syncthreads();
        for (int e = tid; e < 64 * 128; e += 256) {
            int i = e >> 7, u = e & 127;
            float xv = 0.f, mv = 0.f, dv = 0.f;
            if (u < nv) {
                size_t gb = ((size_t)(b * 3 * 64) + i) * 1000 + t0 + u;
                xv = inp[gb];
                mv = inp[gb + 64 * 1000];
                dv = inp[gb + 2 * 64 * 1000];
            }
            sx[i * 129 + u] = xv; smk[i * 129 + u] = mv; sd[i * 129 + u] = dv;
        }
        __syncthreads();
        for (int e = tid; e < 64 * 128; e += 256) {
            int j = e >> 7, u = e & 127;
            float acc = bdgx[j];
            #pragma unroll 8
            for (int k = 0; k < 64; k++) acc += sd[k * 129 + u] * sW[k * 64 + j];
            sg[j * 129 + u] = __expf(-fmaxf(acc, 0.f));
        }
        __syncthreads();
        if (tid < 64) {
            const int i = tid;
            for (int u = 0; u < nv; u++) {
                float mv = smk[i * 129 + u], xv = sx[i * 129 + u], gv = sg[i * 129 + u];
                if (mv > 0.f) xl = xv;
                sx[i * 129 + u] = mv * xv + (1.f - mv) * (gv * xl + (1.f - gv) * xmn);
            }
        }
        __syncthreads();
        for (int e = tid; e < 64 * 128; e += 256) {
            int i = e >> 7, u = e & 127;
            if (u < nv) g_ximp[((size_t)(b * 64) + i) * 1000 + t0 + u] = sx[i * 129 + u];
        }
    }
}

// ============================================================================
// K2 v3: pre-activations, dual-gate weight pairs, t-tile 32.
// smem 88KB -> 2 CTAs/SM (occupancy fix vs v2's 114KB @ 1 CTA/SM).
// ============================================================================
__device__ __forceinline__ void gemm_dual(const float* __restrict__ s,
                                          const float* __restrict__ sWa,
                                          const float* __restrict__ sWb,
                                          ull accA[8], ull accB[8],
                                          int h, int base)
{
    #pragma unroll 4
    for (int k = 0; k < 64; k++) {
        float wa = sWa[k * 128 + h];
        float wb = sWb[k * 128 + h];
        ull wa2 = pk2(wa, wa);
        ull wb2 = pk2(wb, wb);
        const ulonglong2* row = (const ulonglong2*)(s + k * 32 + base);
        #pragma unroll
        for (int j = 0; j < 4; j++) {
            ulonglong2 v = row[j];
            fma2(accA[2 * j],     v.x, wa2);
            fma2(accA[2 * j + 1], v.y, wa2);
            fma2(accB[2 * j],     v.x, wb2);
            fma2(accB[2 * j + 1], v.y, wb2);
        }
    }
}

__device__ __forceinline__ void gemm_one(const float* __restrict__ s,
                                         const float* __restrict__ sW,
                                         ull acc[8], int h, int base)
{
    #pragma unroll 4
    for (int k = 0; k < 64; k++) {
        float w = sW[k * 128 + h];
        ull w2 = pk2(w, w);
        const ulonglong2* row = (const ulonglong2*)(s + k * 32 + base);
        #pragma unroll
        for (int j = 0; j < 4; j++) {
            ulonglong2 v = row[j];
            fma2(acc[2 * j],     v.x, w2);
            fma2(acc[2 * j + 1], v.y, w2);
        }
    }
}

__device__ __forceinline__ void store_pre(const ull acc[8],
                                          int b, int t0, int base, int h, int c, float bias)
{
    #pragma unroll
    for (int j = 0; j < 8; j++) {
        float2 a = up2(acc[j]);
        int u = base + 2 * j;
        size_t adr = ((size_t)b * 1000 + t0 + u) * 512 + c * 128 + h;
        if (t0 + u < 1000)     g_pre[adr]       = a.x + bias;
        if (t0 + u + 1 < 1000) g_pre[adr + 512] = a.y + bias;
    }
}

__global__ void __launch_bounds__(256) k2_pre(
    const float* __restrict__ inp,
    const float* __restrict__ Wdgh, const float* __restrict__ bdgh,
    const float* __restrict__ Wxz,  const float* __restrict__ Wmz, const float* __restrict__ bmz,
    const float* __restrict__ Wxr,  const float* __restrict__ Wmr,
    const float* __restrict__ Wxh,  const float* __restrict__ Wmh, const float* __restrict__ bmh)
{
    extern __shared__ float sm_[];
    float* sx  = sm_;           // 64k x 32t
    float* sm2 = sx + 2048;
    float* sd  = sm2 + 2048;
    float* sWa = sd + 2048;     // 64 x 128
    float* sWb = sWa + 8192;    // 64 x 128
    const int t0 = blockIdx.x * 32, b = blockIdx.y;
    const int tid = threadIdx.x, h = tid & 127, base = (tid >> 7) * 16;

    // load data tiles
    for (int e = tid; e < 2048; e += 256) {
        int k = e >> 5, u = e & 31;
        int t = t0 + u;
        float xv = 0.f, mv = 0.f, dv = 0.f;
        if (t < 1000) {
            xv = g_ximp[((size_t)(b * 64) + k) * 1000 + t];
            size_t gb = ((size_t)(b * 3 * 64) + k) * 1000 + t;
            mv = inp[gb + 64 * 1000];
            dv = inp[gb + 2 * 64 * 1000];
        }
        sx[k * 32 + u] = xv; sm2[k * 32 + u] = mv; sd[k * 32 + u] = dv;
    }

    // ---- pass ZR over x ----
    for (int e = tid; e < 8192; e += 256) { sWa[e] = Wxz[e]; sWb[e] = Wxr[e]; }
    __syncthreads();

    ull accZ[8], accR[8];
    #pragma unroll
    for (int j = 0; j < 8; j++) { accZ[j] = 0ull; accR[j] = 0ull; }
    gemm_dual(sx, sWa, sWb, accZ, accR, h, base);
    __syncthreads();

    // ---- pass ZR over m ----
    for (int e = tid; e < 8192; e += 256) { sWa[e] = Wmz[e]; sWb[e] = Wmr[e]; }
    __syncthreads();
    gemm_dual(sm2, sWa, sWb, accZ, accR, h, base);
    store_pre(accZ, b, t0, base, h, 1, bmz[h]);
    store_pre(accR, b, t0, base, h, 2, 0.f);
    __syncthreads();

    // ---- pass H: x@Wxh + m@Wmh (both weights resident) ----
    for (int e = tid; e < 8192; e += 256) { sWa[e] = Wxh[e]; sWb[e] = Wmh[e]; }
    __syncthreads();
    ull accH[8];
    #pragma unroll
    for (int j = 0; j < 8; j++) accH[j] = 0ull;
    gemm_one(sx,  sWa, accH, h, base);
    gemm_one(sm2, sWb, accH, h, base);
    store_pre(accH, b, t0, base, h, 3, bmh[h]);
    __syncthreads();

    // ---- pass gamma: d@Wdgh ----
    for (int e = tid; e < 8192; e += 256) sWa[e] = Wdgh[e];
    __syncthreads();
    ull accG[8];
    #pragma unroll
    for (int j = 0; j < 8; j++) accG[j] = 0ull;
    gemm_one(sd, sWa, accG, h, base);
    {
        float bb = bdgh[h];
        #pragma unroll
        for (int j = 0; j < 8; j++) {
            float2 a = up2(accG[j]);
            int u = base + 2 * j;
            size_t adr = ((size_t)b * 1000 + t0 + u) * 512 + h;
            if (t0 + u < 1000)     g_pre[adr]       = __expf(-fmaxf(a.x + bb, 0.f));
            if (t0 + u + 1 < 1000) g_pre[adr + 512] = __expf(-fmaxf(a.y + bb, 0.f));
        }
    }
}

// ============================================================================
// K3 v6: R14 winner + Whh smem re-layout so stage C fetches its two weight
// pairs with ONE LDS.128 (row-pair interleaved: swh[q*128 + 2p] = row 2q,
// swh[q*128 + 2p + 1] = row 2q+1, both at column pair p).
// ============================================================================
__global__ void __launch_bounds__(256, 1) k3_rec(
    const float* __restrict__ Whz, const float* __restrict__ Whr,
    const float* __restrict__ Whh, float* __restrict__ hs)
{
    extern __shared__ ull smk3[];
    ull* swh  = smk3;            // 8192: interleaved row-pairs of Whh
    ull* shd0 = swh + 8192;      // 128: gamma-scaled h, duplicated pairs, batch 0
    ull* shd1 = shd0 + 128;      // 128: batch 1
    ull* srh0 = shd1 + 128;      // 128: r*h duplicated, batch 0
    ull* srh1 = srh0 + 128;      // 128: batch 1
    ull* sred = srh1 + 128;      // 4*256 partials

    const int tid = threadIdx.x;
    const int p = tid & 63, jg = tid >> 6;
    const int jb = jg * 32;
    const int bg0 = blockIdx.x * 2;

    // z/r weight slices in registers
    ull wz[32], wr[32];
    #pragma unroll
    for (int j = 0; j < 32; j++) {
        int row = (jb + j) * 128 + 2 * p;
        wz[j] = *(const ull*)(Whz + row);
        wr[j] = *(const ull*)(Whr + row);
    }
    // Whh staged to smem, row-pair interleaved:
    // swh[q*128 + 2*pp + half] = (Whh[2q+half][2pp], Whh[2q+half][2pp+1])
    for (int e = tid; e < 8192; e += 256) {
        int q = e >> 7, idx = e & 127;
        int pp = idx >> 1, half = idx & 1;
        swh[e] = *(const ull*)(Whh + (2 * q + half) * 128 + 2 * pp);
    }
    // init h = 0
    shd0[tid & 127] = 0ull;
    shd1[tid & 127] = 0ull;

    // element identity
    const int be = tid >> 7, he = tid & 127;
    const int pe = he >> 1, comp = he & 1;
    const int bge = bg0 + be;
    ull* shdE = be ? shd1 : shd0;
    ull* srhE = be ? srh1 : srh0;

    float hbar = 0.f;
    float cz, cr, ch;
    {
        size_t adr = ((size_t)bge * 1000) * 512 + he;
        cz = g_pre[adr + 128];
        cr = g_pre[adr + 256];
        ch = g_pre[adr + 384];
    }
    float zv = 0.f;
    __syncthreads();

    for (int t = 0; t < 1000; t++) {
        // prefetch pre(t+1) for this element
        int tn = (t + 1 < 1000) ? t + 1 : 999;
        size_t adr = ((size_t)bge * 1000 + tn) * 512 + he;
        float ng = g_pre[adr];
        float nz = g_pre[adr + 128];
        float nr = g_pre[adr + 256];
        float nh = g_pre[adr + 384];

        // ---- stage B: z/r partial dots (LDS.128 broadcast reads) ----
        ull az0 = 0, az1 = 0, ar0 = 0, ar1 = 0;
        #pragma unroll
        for (int q = 0; q < 16; q++) {
            ulonglong2 h0 = *(const ulonglong2*)&shd0[jb + 2 * q];
            ulonglong2 h1 = *(const ulonglong2*)&shd1[jb + 2 * q];
            fma2(az0, h0.x, wz[2 * q]); fma2(az0, h0.y, wz[2 * q + 1]);
            fma2(ar0, h0.x, wr[2 * q]); fma2(ar0, h0.y, wr[2 * q + 1]);
            fma2(az1, h1.x, wz[2 * q]); fma2(az1, h1.y, wz[2 * q + 1]);
            fma2(ar1, h1.x, wr[2 * q]); fma2(ar1, h1.y, wr[2 * q + 1]);
        }
        sred[0 * 256 + tid] = az0; sred[1 * 256 + tid] = az1;
        sred[2 * 256 + tid] = ar0; sred[3 * 256 + tid] = ar1;
        __syncthreads();   // BAR1

        // ---- epilogue 1 (all 256 threads): z, r, publish r*h ----
        {
            float zs = 0.f, rs = 0.f;
            #pragma unroll
            for (int g = 0; g < 4; g++) {
                zs += ((const float*)&sred[be * 256 + g * 64 + pe])[comp];
                rs += ((const float*)&sred[(2 + be) * 256 + g * 64 + pe])[comp];
            }
            zv = sigf(cz + zs);
            float rv = sigf(cr + rs);
            float rh = rv * hbar;
            srhE[2 * pe + comp] = pk2(rh, rh);
        }
        __syncthreads();   // BAR2

        // ---- stage C: h_tilde partial dots (Whh pairs via one LDS.128) ----
        ull ah0 = 0, ah1 = 0;
        #pragma unroll
        for (int q = 0; q < 16; q++) {
            ulonglong2 q0 = *(const ulonglong2*)&srh0[jb + 2 * q];
            ulonglong2 q1 = *(const ulonglong2*)&srh1[jb + 2 * q];
            ulonglong2 wv = *(const ulonglong2*)&swh[(jg * 16 + q) * 128 + 2 * p];
            fma2(ah0, q0.x, wv.x); fma2(ah0, q0.y, wv.y);
            fma2(ah1, q1.x, wv.x); fma2(ah1, q1.y, wv.y);
        }
        sred[0 * 256 + tid] = ah0; sred[1 * 256 + tid] = ah1;
        __syncthreads();   // BAR3

        // ---- epilogue 2: tanh, h update, store, publish gamma(t+1)*h ----
        {
            float hsum = 0.f;
            #pragma unroll
            for (int g = 0; g < 4; g++)
                hsum += ((const float*)&sred[be * 256 + g * 64 + pe])[comp];
            float ht = tanhf_(ch + hsum);
            float hn = (1.f - zv) * hbar + zv * ht;
            hs[((size_t)bge * 1000 + t) * 128 + he] = hn;
            hbar = ng * hn;
            shdE[2 * pe + comp] = pk2(hbar, hbar);
            cz = nz; cr = nr; ch = nh;
        }
        __syncthreads();   // BAR4
    }
}

// ============================================================================
// K4: y = sigmoid(hs @ W_hy + b_hy). (unchanged)
// ============================================================================
__global__ void __launch_bounds__(256) k4_out(
    const float* __restrict__ hs, const float* __restrict__ Why,
    const float* __restrict__ bhy, float* __restrict__ ys)
{
    extern __shared__ float sm_[];
    float* sh = sm_;               // 128 x 68 (t fast)
    float* sW = sh + 128 * 68;     // 128 x 64
    const int t0 = blockIdx.x * 64, b = blockIdx.y;
    const int tid = threadIdx.x;

    for (int e = tid; e < 8192; e += 256) sW[e] = Why[e];
    for (int e = tid; e < 8192; e += 256) {
        int u = e >> 7, h = e & 127;
        int t = t0 + u;
        sh[h * 68 + u] = (t < 1000) ? hs[((size_t)b * 1000 + t) * 128 + h] : 0.f;
    }
    __syncthreads();

    const int o = tid & 63, q = tid >> 6;
    const int base = q * 16;
    ull acc[8];
    #pragma unroll
    for (int j = 0; j < 8; j++) acc[j] = 0ull;

    for (int h = 0; h < 128; h++) {
        float wv = sW[h * 64 + o];
        ull w2 = pk2(wv, wv);
        const ulonglong2* row = (const ulonglong2*)(sh + h * 68 + base);
        #pragma unroll
        for (int j = 0; j < 4; j++) {
            ulonglong2 v = row[j];
            fma2(acc[2 * j],     v.x, w2);
            fma2(acc[2 * j + 1], v.y, w2);
        }
    }
    float bb = bhy[o];
    #pragma unroll
    for (int j = 0; j < 8; j++) {
        float2 a = up2(acc[j]);
        int t = t0 + base + 2 * j;
        if (t < 1000)     ys[((size_t)b * 1000 + t) * 64 + o]     = sigf(a.x + bb);
        if (t + 1 < 1000) ys[((size_t)b * 1000 + t + 1) * 64 + o] = sigf(a.y + bb);
    }
}

// ============================================================================
extern "C" void kernel_launch(void* const* d_in, const int* in_sizes, int n_in,
                              void* d_out, int out_size)
{
    const float* inp   = (const float*)d_in[0];
    const float* xmean = (const float*)d_in[1];
    const float* Wdgx  = (const float*)d_in[2];
    const float* bdgx  = (const float*)d_in[3];
    const float* Wdgh  = (const float*)d_in[4];
    const float* bdgh  = (const float*)d_in[5];
    const float* Wxz   = (const float*)d_in[6];
    const float* Whz   = (const float*)d_in[7];
    const float* Wmz   = (const float*)d_in[8];
    const float* bmz   = (const float*)d_in[9];
    const float* Wxr   = (const float*)d_in[10];
    const float* Whr   = (const float*)d_in[11];
    const float* Wmr   = (const float*)d_in[12];
    const float* Wxh   = (const float*)d_in[13];
    const float* Whh   = (const float*)d_in[14];
    const float* Wmh   = (const float*)d_in[15];
    const float* bmh   = (const float*)d_in[16];
    const float* Why   = (const float*)d_in[17];
    const float* bhy   = (const float*)d_in[18];

    float* ys = (float*)d_out;                        // (B,T,64)
    float* hs = ys + (size_t)256 * 1000 * 64;         // (B,T,128)

    const int K1_SMEM = (4 * 64 * 129 + 64 * 64) * 4;      // 148480 B
    const int K2_SMEM = (3 * 2048 + 2 * 8192) * 4;         // 90112 B
    const int K3_SMEM = (8192 + 4 * 128 + 4 * 256) * 8;    // 77824 B
    const int K4_SMEM = (128 * 68 + 8192) * 4;             // 67584 B
    cudaFuncSetAttribute(k1_impute, cudaFuncAttributeMaxDynamicSharedMemorySize, K1_SMEM);
    cudaFuncSetAttribute(k2_pre,    cudaFuncAttributeMaxDynamicSharedMemorySize, K2_SMEM);
    cudaFuncSetAttribute(k3_rec,    cudaFuncAttributeMaxDynamicSharedMemorySize, K3_SMEM);
    cudaFuncSetAttribute(k4_out,    cudaFuncAttributeMaxDynamicSharedMemorySize, K4_SMEM);

    k1_impute<<<256, 256, K1_SMEM>>>(inp, xmean, Wdgx, bdgx);

    dim3 g2(32, 256);
    k2_pre<<<g2, 256, K2_SMEM>>>(inp, Wdgh, bdgh, Wxz, Wmz, bmz, Wxr, Wmr, Wxh, Wmh, bmh);

    k3_rec<<<128, 256, K3_SMEM>>>(Whz, Whr, Whh, hs);

    dim3 g4(16, 256);
    k4_out<<<g4, 256, K4_SMEM>>>(hs, Why, bhy, ys);
}